// round 2
// baseline (speedup 1.0000x reference)
#include <cuda_runtime.h>
#include <math.h>

// Problem constants
#define CV 10000   // vocab
#define CE 512     // embed
#define CH 1024    // hidden
#define CK 2048    // key feature dim
#define CB 64      // batch
#define CS 196     // feature seq len
#define CT 15      // decode steps (T-1)

// ---------------- scratch layout (floats) ----------------
#define OFF_XEMB   0u                     // 960*512
#define OFF_XSEQ   491520u                // 960*1024
#define OFF_KEYS   1474560u               // 12544*1024
#define OFF_E      14319616u              // 12544
#define OFF_W      14332160u              // 12544
#define OFF_QP     14344704u              // 4*64*1024
#define OFF_CTX    14606848u              // 64*2048
#define OFF_INP    14737920u              // 64*2048
#define OFF_H      14868992u              // 4*64*1024
#define OFF_GIP    15131136u              // 8*64*3072
#define OFF_GHP    16704000u              // 4*64*3072
#define OFF_FC0P   17490432u              // 8*64*1024
#define OFF_FC2P   18014720u              // 4*64*10048
#define SCRATCH_TOTAL 20587008u

__device__ __align__(16) float g_scratch[SCRATCH_TOTAL];

// fast-but-accurate tanh via HW EX2 (rel err ~1e-6)
__device__ __forceinline__ float fast_tanh(float x) {
    float e = __expf(2.0f * x);
    return 1.0f - 2.0f / (1.0f + e);
}

// ---------------- zero kernel ----------------
__global__ void zerok(float* p, int n) {
    int i = blockIdx.x * 256 + threadIdx.x;
    if (i < n) p[i] = 0.0f;
}

// ---------------- embedding gather ----------------
// xemb[m=(b*15+t), :] = emb[token(b,t), :]   (512 floats per row)
__global__ void gather_emb(const float* __restrict__ emb,
                           const int* __restrict__ captions,
                           const int* __restrict__ sos,
                           float* __restrict__ xemb) {
    int m = blockIdx.x;
    int b = m / CT, t = m % CT;
    int tok = (t == 0) ? sos[0] : captions[b * 16 + t];
    const float4* src = (const float4*)(emb + (size_t)tok * CE);
    float4* dst = (float4*)(xemb + (size_t)m * CE);
    dst[threadIdx.x] = src[threadIdx.x];   // 128 threads * 4 floats = 512
}

// ---------------- generic SGEMM with optional split-K ----------------
// C[m,n] = sum_k A[m,k] * B(k,n)  ;  BT=false: B is [K,N] row-major (NN)
//                                    BT=true : B is [N,K] row-major (NT)
// gridDim.z splits K; block z writes to C + z*zstride (no bias when split).
// Tiles: BM = TM*16, BN = 64, BK = 16, 256 threads, each thread TM x 4 outputs.
template<int TM, bool BT>
__global__ void __launch_bounds__(256)
sgemm(const float* __restrict__ A, const float* __restrict__ B,
      const float* __restrict__ bias, float* __restrict__ C,
      int M, int N, int K, int ldc, int zstride) {
    constexpr int BM = TM * 16;
    constexpr int BN = 64;
    constexpr int BK = 16;
    __shared__ float As[BK][BM + 4];
    __shared__ float Bs[BK][BN + 4];

    int tid = threadIdx.x;
    int tx = tid & 15, ty = tid >> 4;
    int bn = blockIdx.x * BN;
    int bm = blockIdx.y * BM;
    int kper = K / gridDim.z;
    int k0 = blockIdx.z * kper;
    int kend = k0 + kper;
    C += (size_t)blockIdx.z * zstride;

    float acc[TM][4];
#pragma unroll
    for (int i = 0; i < TM; i++)
#pragma unroll
        for (int j = 0; j < 4; j++) acc[i][j] = 0.0f;

    for (int k = k0; k < kend; k += BK) {
        // load A tile: BM x BK, float4 along K
#pragma unroll
        for (int i = tid; i < BM * 4; i += 256) {
            int row = i >> 2;
            int kc = (i & 3) * 4;
            int gr = bm + row; if (gr >= M) gr = M - 1;   // clamp; OOB outputs masked at store
            float4 v = *(const float4*)(A + (size_t)gr * K + k + kc);
            As[kc + 0][row] = v.x; As[kc + 1][row] = v.y;
            As[kc + 2][row] = v.z; As[kc + 3][row] = v.w;
        }
        // load B tile into Bs[k][n]
        if (!BT) {
            int krow = tid >> 4;
            int nc = (tid & 15) * 4;
            int gcol = bn + nc;
            const float* bp = B + (size_t)(k + krow) * N + gcol;
            float4 v;
            if (gcol + 3 < N) v = *(const float4*)bp;
            else {
                v.x = (gcol + 0 < N) ? bp[0] : 0.0f;
                v.y = (gcol + 1 < N) ? bp[1] : 0.0f;
                v.z = (gcol + 2 < N) ? bp[2] : 0.0f;
                v.w = (gcol + 3 < N) ? bp[3] : 0.0f;
            }
            Bs[krow][nc + 0] = v.x; Bs[krow][nc + 1] = v.y;
            Bs[krow][nc + 2] = v.z; Bs[krow][nc + 3] = v.w;
        } else {
            int row = tid >> 2;          // n within tile
            int kc = (tid & 3) * 4;
            int gn = bn + row;
            float4 v = make_float4(0.f, 0.f, 0.f, 0.f);
            if (gn < N) v = *(const float4*)(B + (size_t)gn * K + k + kc);
            Bs[kc + 0][row] = v.x; Bs[kc + 1][row] = v.y;
            Bs[kc + 2][row] = v.z; Bs[kc + 3][row] = v.w;
        }
        __syncthreads();
#pragma unroll
        for (int kk = 0; kk < BK; kk++) {
            float a[TM];
#pragma unroll
            for (int i4 = 0; i4 < TM / 4; i4++) {
                float4 av = *(const float4*)&As[kk][ty * TM + i4 * 4];
                a[i4 * 4 + 0] = av.x; a[i4 * 4 + 1] = av.y;
                a[i4 * 4 + 2] = av.z; a[i4 * 4 + 3] = av.w;
            }
            float4 bv = *(const float4*)&Bs[kk][tx * 4];
            float bb[4] = {bv.x, bv.y, bv.z, bv.w};
#pragma unroll
            for (int i = 0; i < TM; i++)
#pragma unroll
                for (int j = 0; j < 4; j++)
                    acc[i][j] = fmaf(a[i], bb[j], acc[i][j]);
        }
        __syncthreads();
    }
#pragma unroll
    for (int i = 0; i < TM; i++) {
        int row = bm + ty * TM + i;
        if (row < M) {
#pragma unroll
            for (int j = 0; j < 4; j++) {
                int col = bn + tx * 4 + j;
                if (col < N)
                    C[(size_t)row * ldc + col] = acc[i][j] + (bias ? bias[col] : 0.0f);
            }
        }
    }
}

// ---------------- reduce split-K partials + bias ----------------
__global__ void reduce_bias(const float* __restrict__ part, const float* __restrict__ bias,
                            float* __restrict__ out, int M, int N, int ldp,
                            int zcount, int zstride, int ldout) {
    int idx = blockIdx.x * 256 + threadIdx.x;
    if (idx >= M * N) return;
    int row = idx / N, col = idx - row * N;
    float s = bias[col];
    for (int z = 0; z < zcount; z++)
        s += part[(size_t)z * zstride + (size_t)row * ldp + col];
    out[(size_t)row * ldout + col] = s;
}

// ---------------- attention energies ----------------
// e[b,s] = bv + sum_h v[h] * tanh( (bq[h] + sum_z qp[z,b,h]) + keys[b,s,h] )
__global__ void e_kernel(const float* __restrict__ qp, const float* __restrict__ bq,
                         const float* __restrict__ keys, const float* __restrict__ v,
                         const float* __restrict__ bv, float* __restrict__ e) {
    int s = blockIdx.x, b = blockIdx.y, tid = threadIdx.x;
    const float* krow = keys + ((size_t)b * CS + s) * CH;
    float partial = 0.0f;
    for (int h = tid; h < CH; h += 128) {
        float q = bq[h];
#pragma unroll
        for (int z = 0; z < 4; z++) q += qp[z * (CB * CH) + b * CH + h];
        partial += v[h] * fast_tanh(q + krow[h]);
    }
#pragma unroll
    for (int o = 16; o > 0; o >>= 1) partial += __shfl_xor_sync(0xffffffffu, partial, o);
    __shared__ float ws[4];
    if ((tid & 31) == 0) ws[tid >> 5] = partial;
    __syncthreads();
    if (tid == 0) e[b * CS + s] = ws[0] + ws[1] + ws[2] + ws[3] + bv[0];
}

// ---------------- softmax over S + copy x_t into inp[:, :H] ----------------
__global__ void softmax_copy(const float* __restrict__ e, float* __restrict__ w,
                             const float* __restrict__ xseq, float* __restrict__ inp, int t) {
    int b = blockIdx.x, tid = threadIdx.x;
    __shared__ float sh[256];
    float v = (tid < CS) ? e[b * CS + tid] : -1e30f;
    sh[tid] = v; __syncthreads();
    for (int o = 128; o > 0; o >>= 1) { if (tid < o) sh[tid] = fmaxf(sh[tid], sh[tid + o]); __syncthreads(); }
    float m = sh[0]; __syncthreads();
    float ex = (tid < CS) ? __expf(v - m) : 0.0f;
    sh[tid] = ex; __syncthreads();
    for (int o = 128; o > 0; o >>= 1) { if (tid < o) sh[tid] += sh[tid + o]; __syncthreads(); }
    float s = sh[0];
    if (tid < CS) w[b * CS + tid] = ex / s;
    const float* src = xseq + ((size_t)b * CT + t) * CH;
    float* dst = inp + (size_t)b * (2 * CH);
    for (int i = tid; i < CH; i += 256) dst[i] = src[i];
}

// ---------------- context: ctx[b,k] = sum_s w[b,s]*features[b,s,k] ----------------
__global__ void ctx_kernel(const float* __restrict__ w, const float* __restrict__ feat,
                           float* __restrict__ ctx) {
    int b = blockIdx.y;
    int k = blockIdx.x * 256 + threadIdx.x;   // grid.x = 8 -> 2048
    __shared__ float ws[CS];
    if (threadIdx.x < CS) ws[threadIdx.x] = w[b * CS + threadIdx.x];
    __syncthreads();
    const float* f = feat + (size_t)b * CS * CK + k;
    float acc = 0.0f;
#pragma unroll 4
    for (int s = 0; s < CS; s++) acc = fmaf(ws[s], f[(size_t)s * CK], acc);
    ctx[b * CK + k] = acc;
}

// ---------------- GRU cell update (reduces split-K gate partials) ----------------
__global__ void gru_update(const float* __restrict__ gip, int zi,
                           const float* __restrict__ ghp, int zh,
                           const float* __restrict__ bi, const float* __restrict__ bh,
                           float* __restrict__ h) {
    int idx = blockIdx.x * 256 + threadIdx.x;   // 64*1024
    int b = idx >> 10, j = idx & 1023;
    float ir = bi[j], iz = bi[CH + j], in_ = bi[2 * CH + j];
    float hr = bh[j], hz = bh[CH + j], hn = bh[2 * CH + j];
    int base = b * 3 * CH;
    for (int z = 0; z < zi; z++) {
        const float* p = gip + (size_t)z * (CB * 3 * CH) + base;
        ir += p[j]; iz += p[CH + j]; in_ += p[2 * CH + j];
    }
    for (int z = 0; z < zh; z++) {
        const float* p = ghp + (size_t)z * (CB * 3 * CH) + base;
        hr += p[j]; hz += p[CH + j]; hn += p[2 * CH + j];
    }
    float r = 1.0f / (1.0f + expf(-(ir + hr)));
    float zz = 1.0f / (1.0f + expf(-(iz + hz)));
    float n = tanhf(in_ + r * hn);
    h[idx] = (1.0f - zz) * n + zz * h[idx];
}

// ---------------- host launcher ----------------
extern "C" void kernel_launch(void* const* d_in, const int* in_sizes, int n_in,
                              void* d_out, int out_size) {
    const float* features = (const float*)d_in[0];
    const int*   captions = (const int*)d_in[1];
    const int*   sos      = (const int*)d_in[2];
    const float* emb      = (const float*)d_in[3];
    const float* fc1_W    = (const float*)d_in[4];
    const float* fc1_b    = (const float*)d_in[5];
    const float* attn_Wq  = (const float*)d_in[6];
    const float* attn_bq  = (const float*)d_in[7];
    const float* attn_Wk  = (const float*)d_in[8];
    const float* attn_bk  = (const float*)d_in[9];
    const float* attn_v   = (const float*)d_in[10];
    const float* attn_bv  = (const float*)d_in[11];
    const float* fc0_W    = (const float*)d_in[12];
    const float* fc0_b    = (const float*)d_in[13];
    const float* Wi0      = (const float*)d_in[14];
    const float* Wh0      = (const float*)d_in[15];
    const float* bi0      = (const float*)d_in[16];
    const float* bh0      = (const float*)d_in[17];
    const float* WiL      = (const float*)d_in[18];
    const float* WhL      = (const float*)d_in[19];
    const float* biL      = (const float*)d_in[20];
    const float* bhL      = (const float*)d_in[21];
    const float* fc2_W    = (const float*)d_in[22];
    const float* fc2_b    = (const float*)d_in[23];
    float* out = (float*)d_out;

    float* sc = nullptr;
    cudaGetSymbolAddress((void**)&sc, g_scratch);
    float* xemb = sc + OFF_XEMB;
    float* xseq = sc + OFF_XSEQ;
    float* keys = sc + OFF_KEYS;
    float* ebuf = sc + OFF_E;
    float* wbuf = sc + OFF_W;
    float* qp   = sc + OFF_QP;
    float* ctxr = sc + OFF_CTX;
    float* inp  = sc + OFF_INP;
    float* hbuf = sc + OFF_H;
    float* gip  = sc + OFF_GIP;
    float* ghp  = sc + OFF_GHP;
    float* fc0p = sc + OFF_FC0P;
    float* fc2p = sc + OFF_FC2P;

    // h = 0
    zerok<<<(4 * CB * CH + 255) / 256, 256>>>(hbuf, 4 * CB * CH);

    // x_seq = emb[tokens] @ fc1_W + fc1_b
    gather_emb<<<CB * CT, 128>>>(emb, captions, sos, xemb);
    sgemm<8, false><<<dim3(CH / 64, (CB * CT + 127) / 128, 1), 256>>>(
        xemb, fc1_W, fc1_b, xseq, CB * CT, CH, CE, CH, 0);

    // keys_proj = features @ attn_Wk + attn_bk   (big GEMM)
    sgemm<8, false><<<dim3(CH / 64, (CB * CS) / 128, 1), 256>>>(
        features, attn_Wk, attn_bk, keys, CB * CS, CH, CK, CH, 0);

    float* htop = hbuf + 3 * CB * CH;
    for (int t = 0; t < CT; t++) {
        // q partials (no bias; e_kernel folds bias + reduction)
        sgemm<4, false><<<dim3(CH / 64, 1, 4), 256>>>(
            htop, attn_Wq, nullptr, qp, CB, CH, CH, CH, CB * CH);
        e_kernel<<<dim3(CS, CB), 128>>>(qp, attn_bq, keys, attn_v, attn_bv, ebuf);
        softmax_copy<<<CB, 256>>>(ebuf, wbuf, xseq, inp, t);
        ctx_kernel<<<dim3(CK / 256, CB), 256>>>(wbuf, features, ctxr);
        // fc0: ctx_raw @ fc0_W -> inp[:, H:2H]
        sgemm<4, false><<<dim3(CH / 64, 1, 8), 256>>>(
            ctxr, fc0_W, nullptr, fc0p, CB, CH, CK, CH, CB * CH);
        reduce_bias<<<(CB * CH + 255) / 256, 256>>>(
            fc0p, fc0_b, inp + CH, CB, CH, CH, 8, CB * CH, 2 * CH);
        // GRU layer 0 (input = [x_t | ctx], K = 2H)
        sgemm<4, true><<<dim3(3 * CH / 64, 1, 8), 256>>>(
            inp, Wi0, nullptr, gip, CB, 3 * CH, 2 * CH, 3 * CH, CB * 3 * CH);
        sgemm<4, true><<<dim3(3 * CH / 64, 1, 4), 256>>>(
            hbuf, Wh0, nullptr, ghp, CB, 3 * CH, CH, 3 * CH, CB * 3 * CH);
        gru_update<<<(CB * CH) / 256, 256>>>(gip, 8, ghp, 4, bi0, bh0, hbuf);
        // GRU layers 1..3
        for (int l = 1; l < 4; l++) {
            sgemm<4, true><<<dim3(3 * CH / 64, 1, 4), 256>>>(
                hbuf + (l - 1) * CB * CH, WiL + (size_t)(l - 1) * 3 * CH * CH,
                nullptr, gip, CB, 3 * CH, CH, 3 * CH, CB * 3 * CH);
            sgemm<4, true><<<dim3(3 * CH / 64, 1, 4), 256>>>(
                hbuf + l * CB * CH, WhL + (size_t)(l - 1) * 3 * CH * CH,
                nullptr, ghp, CB, 3 * CH, CH, 3 * CH, CB * 3 * CH);
            gru_update<<<(CB * CH) / 256, 256>>>(
                gip, 4, ghp, 4, biL + (l - 1) * 3 * CH, bhL + (l - 1) * 3 * CH,
                hbuf + l * CB * CH);
        }
        // fc2: logits -> out[:, t, :]
        sgemm<4, false><<<dim3(157, 1, 4), 256>>>(
            htop, fc2_W, nullptr, fc2p, CB, CV, CH, 10048, CB * 10048);
        reduce_bias<<<(CB * CV + 255) / 256, 256>>>(
            fc2p, fc2_b, out + (size_t)t * CV, CB, CV, 10048, 4, CB * 10048, CT * CV);
    }
}

// round 4
// speedup vs baseline: 1.9085x; 1.9085x over previous
#include <cuda_runtime.h>
#include <math.h>

// Problem constants
#define CV 10000
#define CE 512
#define CH 1024
#define CK 2048
#define CB 64
#define CS 196
#define CT 15

// ---------------- scratch layout (floats) ----------------
#define OFF_XEMB   0u            // 960*512
#define OFF_XSEQ   491520u       // 960*1024
#define OFF_KEYS   1474560u      // 12544*1024
#define OFF_E      14319616u     // 12544
#define OFF_W      14332160u     // 12544
#define OFF_QP     14344704u     // 8*64*1024 (STORE_T: [z][b][h])
#define OFF_CTXT   14868992u     // 2048*64
#define OFF_INPT   15000064u     // 2048*64
#define OFF_HT     15131136u     // 4*1024*64
#define OFF_GIP    15393280u     // 4*3072*64
#define OFF_GHP    16179712u     // 4*3072*64
#define OFF_FC0P   16966144u     // 8*1024*64
#define OFF_FC2P   17490432u     // 2*64*10016 ([z][b][v])
#define OFF_WQT    18772480u     // 1024*1024
#define OFF_FC0T   19821056u     // 1024*2048
#define OFF_FC2T   21918208u     // 10000*1024
#define OFF_QS     32158208u     // 64*1024
#define SCRATCH_TOTAL 32223744u

__device__ __align__(16) float g_scratch[SCRATCH_TOTAL];

__device__ __forceinline__ float fast_tanh(float x) {
    float e = __expf(2.0f * x);
    return 1.0f - 2.0f / (1.0f + e);
}

__device__ __forceinline__ float tf32r(float x) {
    unsigned u;
    asm("cvt.rna.tf32.f32 %0, %1;" : "=r"(u) : "f"(x));
    return __uint_as_float(u);
}

__device__ __forceinline__ void mma8(float* c, const unsigned* a, const unsigned* b) {
    asm volatile(
        "mma.sync.aligned.m16n8k8.row.col.f32.tf32.tf32.f32 "
        "{%0,%1,%2,%3}, {%4,%5,%6,%7}, {%8,%9}, {%0,%1,%2,%3};\n"
        : "+f"(c[0]), "+f"(c[1]), "+f"(c[2]), "+f"(c[3])
        : "r"(a[0]), "r"(a[1]), "r"(a[2]), "r"(a[3]), "r"(b[0]), "r"(b[1]));
}

// ---------------- tf32 tensor-core GEMM ----------------
// C[m,n] = sum_k A[m,k] * B[k, bn+n]   (A: [M][K] row-major, lda;
//                                       B: [K][Ntot] row-major, ldb)
// Block tile: 128(m) x 64(n) x 32(k). 8 warps: 4(m) x 2(n), warp tile 32x32.
// Split-K over gridDim.z: block z writes C + z*zstride (bias only valid z=1).
// STORE_T: write C[col*ldc + row] (i.e., output [n][m]); else C[row*ldc + col].
template<bool STORE_T>
__global__ void __launch_bounds__(256)
gemm_tf32(const float* __restrict__ A, const float* __restrict__ B,
          const float* __restrict__ bias, float* __restrict__ C,
          int M, int K, int lda, int ldb, int ldc, size_t zstride)
{
    __shared__ float As[128 * 44];   // [m][k] stride 44 (conflict-free frags, 16B-aligned)
    __shared__ float Bs[32 * 72];    // [k][n] stride 72

    int tid = threadIdx.x;
    int lane = tid & 31, w = tid >> 5;
    int wm = (w & 3) * 32, wn = (w >> 2) * 32;
    int bn = blockIdx.x * 64, bm = blockIdx.y * 128;
    int kper = K / gridDim.z;
    int k0 = blockIdx.z * kper, kend = k0 + kper;
    C += (size_t)blockIdx.z * zstride;

    float acc[2][4][4] = {};
    float4 apf[4], bpf[2];

    // prefetch chunk k0
    {
        int kc = k0;
#pragma unroll
        for (int i = 0; i < 4; i++) {
            int f = tid + i * 256, m = f >> 3, k4 = f & 7;
            int gm = bm + m; if (gm >= M) gm = M - 1;
            apf[i] = *(const float4*)(A + (size_t)gm * lda + kc + k4 * 4);
        }
#pragma unroll
        for (int i = 0; i < 2; i++) {
            int f = tid + i * 256, kr = f >> 4, n4 = f & 15;
            bpf[i] = *(const float4*)(B + (size_t)(kc + kr) * ldb + bn + n4 * 4);
        }
    }

    for (int kc = k0; kc < kend; kc += 32) {
        // STS (with tf32 rounding)
#pragma unroll
        for (int i = 0; i < 4; i++) {
            int f = tid + i * 256, m = f >> 3, k4 = f & 7;
            float4 v = apf[i];
            float4 cv = make_float4(tf32r(v.x), tf32r(v.y), tf32r(v.z), tf32r(v.w));
            *(float4*)&As[m * 44 + k4 * 4] = cv;
        }
#pragma unroll
        for (int i = 0; i < 2; i++) {
            int f = tid + i * 256, kr = f >> 4, n4 = f & 15;
            float4 v = bpf[i];
            float4 cv = make_float4(tf32r(v.x), tf32r(v.y), tf32r(v.z), tf32r(v.w));
            *(float4*)&Bs[kr * 72 + n4 * 4] = cv;
        }
        __syncthreads();
        if (kc + 32 < kend) {
            int kn = kc + 32;
#pragma unroll
            for (int i = 0; i < 4; i++) {
                int f = tid + i * 256, m = f >> 3, k4 = f & 7;
                int gm = bm + m; if (gm >= M) gm = M - 1;
                apf[i] = *(const float4*)(A + (size_t)gm * lda + kn + k4 * 4);
            }
#pragma unroll
            for (int i = 0; i < 2; i++) {
                int f = tid + i * 256, kr = f >> 4, n4 = f & 15;
                bpf[i] = *(const float4*)(B + (size_t)(kn + kr) * ldb + bn + n4 * 4);
            }
        }
        const unsigned* Asu = (const unsigned*)As;
        const unsigned* Bsu = (const unsigned*)Bs;
        int r = lane >> 2, cq = lane & 3;
#pragma unroll
        for (int kk = 0; kk < 4; kk++) {
            unsigned a[2][4], bf[4][2];
#pragma unroll
            for (int t = 0; t < 2; t++) {
                int base = (wm + t * 16 + r) * 44 + kk * 8 + cq;
                a[t][0] = Asu[base];
                a[t][1] = Asu[base + 8 * 44];
                a[t][2] = Asu[base + 4];
                a[t][3] = Asu[base + 8 * 44 + 4];
            }
#pragma unroll
            for (int j = 0; j < 4; j++) {
                int base = (kk * 8 + cq) * 72 + wn + j * 8 + r;
                bf[j][0] = Bsu[base];
                bf[j][1] = Bsu[base + 4 * 72];
            }
#pragma unroll
            for (int t = 0; t < 2; t++)
#pragma unroll
                for (int j = 0; j < 4; j++)
                    mma8(acc[t][j], a[t], bf[j]);
        }
        __syncthreads();
    }

    // store
    int r = lane >> 2, cq = lane & 3;
#pragma unroll
    for (int t = 0; t < 2; t++) {
#pragma unroll
        for (int j = 0; j < 4; j++) {
            int row0 = bm + wm + t * 16 + r;
            int col = bn + wn + j * 8 + cq * 2;
            float* ac = acc[t][j];
            if (STORE_T) {
                if (row0 < M) {
                    C[(size_t)col * ldc + row0] = ac[0];
                    C[(size_t)(col + 1) * ldc + row0] = ac[1];
                }
                if (row0 + 8 < M) {
                    C[(size_t)col * ldc + row0 + 8] = ac[2];
                    C[(size_t)(col + 1) * ldc + row0 + 8] = ac[3];
                }
            } else {
                float b0 = bias ? bias[col] : 0.0f;
                float b1 = bias ? bias[col + 1] : 0.0f;
                if (row0 < M)
                    *(float2*)(C + (size_t)row0 * ldc + col) = make_float2(ac[0] + b0, ac[1] + b1);
                if (row0 + 8 < M)
                    *(float2*)(C + (size_t)(row0 + 8) * ldc + col) = make_float2(ac[2] + b0, ac[3] + b1);
            }
        }
    }
}

// ---------------- misc kernels ----------------
__global__ void zerok(float* p, int n) {
    int i = blockIdx.x * 256 + threadIdx.x;
    if (i < n) p[i] = 0.0f;
}

__global__ void gather_emb(const float* __restrict__ emb,
                           const int* __restrict__ captions,
                           const int* __restrict__ sos,
                           float* __restrict__ xemb) {
    int m = blockIdx.x;
    int b = m / CT, t = m % CT;
    int tok = (t == 0) ? sos[0] : captions[b * 16 + t];
    const float4* src = (const float4*)(emb + (size_t)tok * CE);
    float4* dst = (float4*)(xemb + (size_t)m * CE);
    dst[threadIdx.x] = src[threadIdx.x];
}

// out[C][R] = in[R][C]^T ; block 32x8, 4 rows per thread
__global__ void transpose_k(const float* __restrict__ in, float* __restrict__ out,
                            int R, int Cc) {
    __shared__ float t[32][33];
    int c = blockIdx.x * 32 + threadIdx.x;
    int r = blockIdx.y * 32 + threadIdx.y;
#pragma unroll
    for (int i = 0; i < 4; i++) {
        int rr = r + i * 8;
        if (rr < R && c < Cc) t[threadIdx.y + i * 8][threadIdx.x] = in[(size_t)rr * Cc + c];
    }
    __syncthreads();
    int c2 = blockIdx.y * 32 + threadIdx.x;
    int r2 = blockIdx.x * 32 + threadIdx.y;
#pragma unroll
    for (int i = 0; i < 4; i++) {
        int rr = r2 + i * 8;
        if (rr < Cc && c2 < R) out[(size_t)rr * R + c2] = t[threadIdx.x][threadIdx.y + i * 8];
    }
}

// qsum[b][h] = bq[h] + sum_z qp[z][b][h]
__global__ void qsum_kernel(const float* __restrict__ qp, const float* __restrict__ bq,
                            float* __restrict__ qs) {
    int idx = blockIdx.x * 256 + threadIdx.x;  // 65536
    int h = idx & 1023;
    float s = bq[h];
#pragma unroll
    for (int z = 0; z < 8; z++) s += qp[z * (CB * CH) + idx];
    qs[idx] = s;
}

// e[b,s] = bv + sum_h v[h] * tanh(qs[b,h] + keys[b,s,h])
__global__ void e_kernel(const float* __restrict__ qs, const float* __restrict__ keys,
                         const float* __restrict__ v, const float* __restrict__ bv,
                         float* __restrict__ e) {
    int s = blockIdx.x, b = blockIdx.y, tid = threadIdx.x;
    const float* krow = keys + ((size_t)b * CS + s) * CH;
    const float* qrow = qs + (size_t)b * CH;
    float partial = 0.0f;
    for (int h = tid; h < CH; h += 128)
        partial += v[h] * fast_tanh(qrow[h] + krow[h]);
#pragma unroll
    for (int o = 16; o > 0; o >>= 1) partial += __shfl_xor_sync(0xffffffffu, partial, o);
    __shared__ float ws[4];
    if ((tid & 31) == 0) ws[tid >> 5] = partial;
    __syncthreads();
    if (tid == 0) e[b * CS + s] = ws[0] + ws[1] + ws[2] + ws[3] + bv[0];
}

// softmax over S; also scatter x_t into inpT rows [0,1024)
__global__ void softmax_copy(const float* __restrict__ e, float* __restrict__ w,
                             const float* __restrict__ xseq, float* __restrict__ inpT, int t) {
    int b = blockIdx.x, tid = threadIdx.x;
    __shared__ float sh[256];
    float v = (tid < CS) ? e[b * CS + tid] : -1e30f;
    sh[tid] = v; __syncthreads();
    for (int o = 128; o > 0; o >>= 1) { if (tid < o) sh[tid] = fmaxf(sh[tid], sh[tid + o]); __syncthreads(); }
    float m = sh[0]; __syncthreads();
    float ex = (tid < CS) ? __expf(v - m) : 0.0f;
    sh[tid] = ex; __syncthreads();
    for (int o = 128; o > 0; o >>= 1) { if (tid < o) sh[tid] += sh[tid + o]; __syncthreads(); }
    float s = sh[0];
    if (tid < CS) w[b * CS + tid] = ex / s;
    const float* src = xseq + ((size_t)b * CT + t) * CH;
    for (int i = tid; i < CH; i += 256) inpT[i * CB + b] = src[i];
}

// ctxT[k][b] = sum_s w[b,s]*features[b,s,k]; grid (64,8), block 256 = 32k x 8b
__global__ void ctx_kernel(const float* __restrict__ w, const float* __restrict__ feat,
                           float* __restrict__ ctxT) {
    int kk = threadIdx.x & 31, bb = threadIdx.x >> 5;
    int b = blockIdx.y * 8 + bb;
    int k = blockIdx.x * 32 + kk;
    __shared__ float ws[8][200];
    for (int i = threadIdx.x; i < 8 * CS; i += 256)
        ws[i / CS][i % CS] = w[(blockIdx.y * 8 + i / CS) * CS + i % CS];
    __syncthreads();
    const float* f = feat + ((size_t)b * CS) * CK + k;
    float acc = 0.0f;
#pragma unroll 4
    for (int s = 0; s < CS; s++) acc = fmaf(ws[bb][s], f[(size_t)s * CK], acc);
    ctxT[k * CB + b] = acc;
}

// reduce split-K partials ([M][64] layout) with per-row bias -> out (same layout)
__global__ void reduce64(const float* __restrict__ part, const float* __restrict__ bias,
                         float* __restrict__ out, int z, size_t zstride) {
    int idx = blockIdx.x * 256 + threadIdx.x;
    int row = idx >> 6;
    float s = bias[row];
    for (int zz = 0; zz < z; zz++) s += part[zz * zstride + idx];
    out[idx] = s;
}

// GRU update, transposed layout. gip/ghp: [z][3072][64] (gates r,z,n by row block)
__global__ void gru_update(const float* __restrict__ gip, const float* __restrict__ ghp,
                           const float* __restrict__ bi, const float* __restrict__ bh,
                           float* __restrict__ h) {
    int idx = blockIdx.x * 256 + threadIdx.x;  // 64*1024
    int b = idx & 63, j = idx >> 6;
    float ir = bi[j], iz = bi[CH + j], in_ = bi[2 * CH + j];
    float hr = bh[j], hz = bh[CH + j], hn = bh[2 * CH + j];
#pragma unroll
    for (int z = 0; z < 4; z++) {
        const float* p = gip + (size_t)z * (3 * CH * CB);
        ir += p[j * CB + b]; iz += p[(CH + j) * CB + b]; in_ += p[(2 * CH + j) * CB + b];
        const float* q = ghp + (size_t)z * (3 * CH * CB);
        hr += q[j * CB + b]; hz += q[(CH + j) * CB + b]; hn += q[(2 * CH + j) * CB + b];
    }
    float r = 1.0f / (1.0f + expf(-(ir + hr)));
    float zz = 1.0f / (1.0f + expf(-(iz + hz)));
    float n = tanhf(in_ + r * hn);
    h[idx] = (1.0f - zz) * n + zz * h[idx];
}

// fc2 final reduce: partials [z][b][10016] -> out[b][t][10000]
__global__ void reduce_fc2(const float* __restrict__ p, const float* __restrict__ bias,
                           float* __restrict__ out, int t) {
    int idx = blockIdx.x * 256 + threadIdx.x;
    if (idx >= CB * CV) return;
    int b = idx / CV, v = idx - b * CV;
    float s = bias[v] + p[(size_t)b * 10016 + v] + p[(size_t)CB * 10016 + (size_t)b * 10016 + v];
    out[((size_t)b * CT + t) * CV + v] = s;
}

// ---------------- host launcher ----------------
extern "C" void kernel_launch(void* const* d_in, const int* in_sizes, int n_in,
                              void* d_out, int out_size) {
    const float* features = (const float*)d_in[0];
    const int*   captions = (const int*)d_in[1];
    const int*   sos      = (const int*)d_in[2];
    const float* emb      = (const float*)d_in[3];
    const float* fc1_W    = (const float*)d_in[4];
    const float* fc1_b    = (const float*)d_in[5];
    const float* attn_Wq  = (const float*)d_in[6];
    const float* attn_bq  = (const float*)d_in[7];
    const float* attn_Wk  = (const float*)d_in[8];
    const float* attn_bk  = (const float*)d_in[9];
    const float* attn_v   = (const float*)d_in[10];
    const float* attn_bv  = (const float*)d_in[11];
    const float* fc0_W    = (const float*)d_in[12];
    const float* fc0_b    = (const float*)d_in[13];
    const float* Wi0      = (const float*)d_in[14];
    const float* Wh0      = (const float*)d_in[15];
    const float* bi0      = (const float*)d_in[16];
    const float* bh0      = (const float*)d_in[17];
    const float* WiL      = (const float*)d_in[18];
    const float* WhL      = (const float*)d_in[19];
    const float* biL      = (const float*)d_in[20];
    const float* bhL      = (const float*)d_in[21];
    const float* fc2_W    = (const float*)d_in[22];
    const float* fc2_b    = (const float*)d_in[23];
    float* out = (float*)d_out;

    float* sc = nullptr;
    cudaGetSymbolAddress((void**)&sc, g_scratch);
    float* xemb = sc + OFF_XEMB;
    float* xseq = sc + OFF_XSEQ;
    float* keys = sc + OFF_KEYS;
    float* ebuf = sc + OFF_E;
    float* wbuf = sc + OFF_W;
    float* qp   = sc + OFF_QP;
    float* ctxT = sc + OFF_CTXT;
    float* inpT = sc + OFF_INPT;
    float* hT   = sc + OFF_HT;
    float* gip  = sc + OFF_GIP;
    float* ghp  = sc + OFF_GHP;
    float* fc0p = sc + OFF_FC0P;
    float* fc2p = sc + OFF_FC2P;
    float* WqT  = sc + OFF_WQT;
    float* fc0T = sc + OFF_FC0T;
    float* fc2T = sc + OFF_FC2T;
    float* qs   = sc + OFF_QS;

    zerok<<<(4 * CB * CH + 255) / 256, 256>>>(hT, 4 * CB * CH);
    gather_emb<<<CB * CT, 128>>>(emb, captions, sos, xemb);

    // weight pre-transposes ([k][m] -> [m][k])
    transpose_k<<<dim3(32, 32), dim3(32, 8)>>>(attn_Wq, WqT, CH, CH);
    transpose_k<<<dim3(32, 64), dim3(32, 8)>>>(fc0_W, fc0T, CK, CH);
    transpose_k<<<dim3((CV + 31) / 32, 32), dim3(32, 8)>>>(fc2_W, fc2T, CH, CV);

    // xseq = xemb @ fc1_W + b : A=xemb[960][512], B=fc1_W[512][1024]
    gemm_tf32<false><<<dim3(16, 8, 1), 256>>>(xemb, fc1_W, fc1_b, xseq,
                                              960, CE, CE, CH, CH, 0);
    // keys = features @ attn_Wk + b : A=features[12544][2048], B=Wk[2048][1024]
    gemm_tf32<false><<<dim3(16, 98, 1), 256>>>(features, attn_Wk, attn_bk, keys,
                                               CB * CS, CK, CK, CH, CH, 0);

    float* htopT = hT + 3 * CB * CH;
    for (int t = 0; t < CT; t++) {
        // q partials: A=WqT[1024][1024], B=htopT[1024][64], STORE_T -> qp[z][b][h]
        gemm_tf32<true><<<dim3(1, 8, 8), 256>>>(WqT, htopT, nullptr, qp,
                                                CH, CH, CH, CB, CH, (size_t)CB * CH);
        qsum_kernel<<<256, 256>>>(qp, attn_bq, qs);
        e_kernel<<<dim3(CS, CB), 128>>>(qs, keys, attn_v, attn_bv, ebuf);
        softmax_copy<<<CB, 256>>>(ebuf, wbuf, xseq, inpT, t);
        ctx_kernel<<<dim3(CK / 32, 8), 256>>>(wbuf, features, ctxT);
        // fc0 partials: A=fc0T[1024][2048], B=ctxT[2048][64]
        gemm_tf32<false><<<dim3(1, 8, 8), 256>>>(fc0T, ctxT, nullptr, fc0p,
                                                 CH, CK, CK, CB, CB, (size_t)CB * CH);
        reduce64<<<(CB * CH) / 256, 256>>>(fc0p, fc0_b, inpT + CH * CB, 8, (size_t)CB * CH);
        // GRU layer 0
        gemm_tf32<false><<<dim3(1, 24, 4), 256>>>(Wi0, inpT, nullptr, gip,
                                                  3 * CH, 2 * CH, 2 * CH, CB, CB, (size_t)3 * CH * CB);
        gemm_tf32<false><<<dim3(1, 24, 4), 256>>>(Wh0, hT, nullptr, ghp,
                                                  3 * CH, CH, CH, CB, CB, (size_t)3 * CH * CB);
        gru_update<<<(CB * CH) / 256, 256>>>(gip, ghp, bi0, bh0, hT);
        // GRU layers 1..3
        for (int l = 1; l < 4; l++) {
            gemm_tf32<false><<<dim3(1, 24, 4), 256>>>(
                WiL + (size_t)(l - 1) * 3 * CH * CH, hT + (size_t)(l - 1) * CB * CH,
                nullptr, gip, 3 * CH, CH, CH, CB, CB, (size_t)3 * CH * CB);
            gemm_tf32<false><<<dim3(1, 24, 4), 256>>>(
                WhL + (size_t)(l - 1) * 3 * CH * CH, hT + (size_t)l * CB * CH,
                nullptr, ghp, 3 * CH, CH, CH, CB, CB, (size_t)3 * CH * CB);
            gru_update<<<(CB * CH) / 256, 256>>>(
                gip, ghp, biL + (size_t)(l - 1) * 3 * CH, bhL + (size_t)(l - 1) * 3 * CH,
                hT + (size_t)l * CB * CH);
        }
        // fc2 partials: A=fc2T[10000][1024], B=htopT, STORE_T -> fc2p[z][b][v]
        gemm_tf32<true><<<dim3(1, 79, 2), 256>>>(fc2T, htopT, nullptr, fc2p,
                                                 CV, CH, CH, CB, 10016, (size_t)CB * 10016);
        reduce_fc2<<<(CB * CV + 255) / 256, 256>>>(fc2p, fc2_b, out, t);
    }
}